// round 1
// baseline (speedup 1.0000x reference)
#include <cuda_runtime.h>

// Problem constants (VisualPromptEncoder_49074296324730)
#define BB   8
#define CC   256
#define HH   160
#define WW   160
#define NN   100     // boxes per image
#define NCLS 80      // classes
#define PSTR 161     // padded SMEM row stride (conflict-free scans)

// Scratch: pooled per-box features, layout [B][N][C]  (8*100*256*4 = 819 KB)
__device__ float g_pooled[BB * NN * CC];

// ---------------------------------------------------------------------------
// Kernel 1: per (b,c) plane — build SAT in SMEM, pool all 100 boxes of batch b
// grid = B*C blocks, 160 threads, dyn smem = HH*PSTR*4 = 103040 B
// ---------------------------------------------------------------------------
__global__ void __launch_bounds__(160, 2)
sat_pool_kernel(const float* __restrict__ feat,
                const float* __restrict__ boxes,
                const int*   __restrict__ img_h,
                const int*   __restrict__ img_w)
{
    extern __shared__ float s[];               // [HH][PSTR]
    const int blk = blockIdx.x;                // b*CC + c
    const int b   = blk >> 8;
    const int c   = blk & 255;
    const int tid = threadIdx.x;               // 0..159

    const float* plane = feat + (size_t)blk * (HH * WW);

    // Coalesced load, re-strided to PSTR
    #pragma unroll 4
    for (int i = tid; i < HH * WW; i += 160) {
        int y = i / WW;
        int x = i - y * WW;
        s[y * PSTR + x] = plane[i];
    }
    __syncthreads();

    // Row inclusive scan: thread tid owns row tid. bank = (tid*161 + x)%32 = (tid+x)%32 -> conflict-free
    {
        float run = 0.f;
        const int base = tid * PSTR;
        #pragma unroll 8
        for (int x = 0; x < WW; x++) {
            run += s[base + x];
            s[base + x] = run;
        }
    }
    __syncthreads();

    // Column inclusive scan: thread tid owns column tid. bank = (y + tid)%32 -> conflict-free
    {
        float run = 0.f;
        #pragma unroll 8
        for (int y = 0; y < HH; y++) {
            const int idx = y * PSTR + tid;
            run += s[idx];
            s[idx] = run;
        }
    }
    __syncthreads();

    // Box pooling: thread n < 100 handles box (b, n) for this channel c
    if (tid < NN) {
        const float sx = (float)WW / (float)img_w[0];
        const float sy = (float)HH / (float)img_h[0];
        const float* bx = boxes + ((size_t)b * NN + tid) * 4;
        const float fx1 = floorf(bx[0] * sx);
        const float fy1 = floorf(bx[1] * sy);
        const float fx2 = floorf(bx[2] * sx);
        const float fy2 = floorf(bx[3] * sy);
        const int x1 = (int)fminf(fmaxf(fx1, 0.f), (float)WW);
        const int y1 = (int)fminf(fmaxf(fy1, 0.f), (float)HH);
        const int x2 = (int)fminf(fmaxf(fx2, 0.f), (float)WW);
        const int y2 = (int)fminf(fmaxf(fy2, 0.f), (float)HH);
        const bool valid = (x2 > x1) && (y2 > y1);

        float out = 0.f;
        if (valid) {
            // padded SAT lookup: sp(y,x) = SAT_incl[y-1][x-1] for y,x>0 else 0
            const float s22 = s[(y2 - 1) * PSTR + (x2 - 1)];
            const float s12 = (y1 > 0) ? s[(y1 - 1) * PSTR + (x2 - 1)] : 0.f;
            const float s21 = (x1 > 0) ? s[(y2 - 1) * PSTR + (x1 - 1)] : 0.f;
            const float s11 = (y1 > 0 && x1 > 0) ? s[(y1 - 1) * PSTR + (x1 - 1)] : 0.f;
            const float sum = s22 - s12 - s21 + s11;
            int area = (x2 - x1) * (y2 - y1);
            if (area < 1) area = 1;
            out = sum / (float)area;
        }
        g_pooled[((size_t)b * NN + tid) * CC + c] = out;
    }
}

// ---------------------------------------------------------------------------
// Kernel 2: segment mean per (b, cls) with negative-pixel fallback
// grid = B*NCLS blocks, 256 threads (one per channel)
// ---------------------------------------------------------------------------
__global__ void __launch_bounds__(256)
reduce_kernel(const float* __restrict__ feat,
              const float* __restrict__ boxes,
              const int*   __restrict__ gtc,
              const int*   __restrict__ neg_y,
              const int*   __restrict__ neg_x,
              const int*   __restrict__ img_h,
              const int*   __restrict__ img_w,
              float*       __restrict__ out)
{
    const int blk = blockIdx.x;               // b*NCLS + cls
    const int b   = blk / NCLS;
    const int cls = blk - b * NCLS;
    const int c   = threadIdx.x;              // 0..255

    __shared__ int   s_cls[NN];
    __shared__ float s_val[NN];

    if (c < NN) {
        s_cls[c] = gtc[b * NN + c];
        const float sx = (float)WW / (float)img_w[0];
        const float sy = (float)HH / (float)img_h[0];
        const float* bx = boxes + ((size_t)b * NN + c) * 4;
        const int x1 = (int)fminf(fmaxf(floorf(bx[0] * sx), 0.f), (float)WW);
        const int y1 = (int)fminf(fmaxf(floorf(bx[1] * sy), 0.f), (float)HH);
        const int x2 = (int)fminf(fmaxf(floorf(bx[2] * sx), 0.f), (float)WW);
        const int y2 = (int)fminf(fmaxf(floorf(bx[3] * sy), 0.f), (float)HH);
        s_val[c] = ((x2 > x1) && (y2 > y1)) ? 1.f : 0.f;
    }
    __syncthreads();

    float sum = 0.f;
    float cnt = 0.f;
    const float* pooled_b = g_pooled + (size_t)b * NN * CC;
    #pragma unroll 4
    for (int n = 0; n < NN; n++) {
        if (s_cls[n] == cls && s_val[n] > 0.f) {   // uniform across block
            sum += pooled_b[(size_t)n * CC + c];
            cnt += 1.f;
        }
    }

    float r;
    if (cnt > 0.f) {
        r = sum / cnt;
    } else {
        const int ny = neg_y[b * NCLS + cls];
        const int nx = neg_x[b * NCLS + cls];
        r = feat[(((size_t)b * CC + c) * HH + ny) * WW + nx];
    }
    out[(size_t)blk * CC + c] = r;
}

// ---------------------------------------------------------------------------
extern "C" void kernel_launch(void* const* d_in, const int* in_sizes, int n_in,
                              void* d_out, int out_size)
{
    const float* feat  = (const float*)d_in[0];   // [8,256,160,160] f32
    const float* boxes = (const float*)d_in[1];   // [8,100,4] f32
    const int*   gtc   = (const int*)d_in[2];     // [8,100] i32
    const int*   ngy   = (const int*)d_in[3];     // [8,80] i32
    const int*   ngx   = (const int*)d_in[4];     // [8,80] i32
    const int*   ih    = (const int*)d_in[5];     // scalar
    const int*   iw    = (const int*)d_in[6];     // scalar
    float*       out   = (float*)d_out;           // [8,80,256] f32

    const int smem = HH * PSTR * sizeof(float);   // 103040 B
    cudaFuncSetAttribute(sat_pool_kernel,
                         cudaFuncAttributeMaxDynamicSharedMemorySize, smem);

    sat_pool_kernel<<<BB * CC, 160, smem>>>(feat, boxes, ih, iw);
    reduce_kernel<<<BB * NCLS, 256>>>(feat, boxes, gtc, ngy, ngx, ih, iw, out);
}

// round 2
// speedup vs baseline: 2.2155x; 2.2155x over previous
#include <cuda_runtime.h>

// Problem constants (VisualPromptEncoder_49074296324730)
#define BB   8
#define CC   256
#define HH   160
#define WW   160
#define NN   100     // boxes per image
#define NCLS 80      // classes
#define TROWS 32     // tile rows
#define NTILE 5      // HH / TROWS
#define PSTR 161     // padded SMEM row stride (conflict-free scans)

// Scratch: pooled per-box features, layout [B][N][C]
__device__ float g_pooled[BB * NN * CC];

// ---------------------------------------------------------------------------
// Kernel 1: per (b,c) plane — streaming tiled SAT (32-row tiles), corners only
// grid = B*C blocks, 160 threads, ~26KB static smem -> 8 blocks/SM
// ---------------------------------------------------------------------------
__global__ void __launch_bounds__(160, 8)
sat_pool_kernel(const float* __restrict__ feat,
                const float* __restrict__ boxes,
                const int*   __restrict__ img_h,
                const int*   __restrict__ img_w)
{
    __shared__ float s[TROWS * PSTR];   // tile of row-prefix / SAT rows
    __shared__ float carry[WW];         // running column sums (SAT carry)
    __shared__ float cs[5 * TROWS];     // per-row chunk sums  cs[k*32 + r]
    __shared__ float cv[4 * NN];        // corner SAT values
    __shared__ int   cy[4 * NN];        // corner y (0..160)
    __shared__ int   cx[4 * NN];        // corner x (0..160)

    const int blk = blockIdx.x;         // b*CC + c
    const int b   = blk >> 8;
    const int c   = blk & 255;
    const int tid = threadIdx.x;        // 0..159
    const int r   = tid & 31;           // row within tile for row-scan
    const int k   = tid >> 5;           // chunk (warp) index 0..4

    // ---- setup: box corners (shared across tiles), zero carry/cv ----
    if (tid < WW) carry[tid] = 0.f;
    if (tid < NN) {
        const float sx = (float)WW / (float)img_w[0];
        const float sy = (float)HH / (float)img_h[0];
        const float* bx = boxes + ((size_t)b * NN + tid) * 4;
        const int x1 = (int)fminf(fmaxf(floorf(bx[0] * sx), 0.f), (float)WW);
        const int y1 = (int)fminf(fmaxf(floorf(bx[1] * sy), 0.f), (float)HH);
        const int x2 = (int)fminf(fmaxf(floorf(bx[2] * sx), 0.f), (float)WW);
        const int y2 = (int)fminf(fmaxf(floorf(bx[3] * sy), 0.f), (float)HH);
        cy[tid          ] = y2; cx[tid          ] = x2;   // s22
        cy[tid +     NN ] = y1; cx[tid +     NN ] = x2;   // s12
        cy[tid + 2 * NN ] = y2; cx[tid + 2 * NN ] = x1;   // s21
        cy[tid + 3 * NN ] = y1; cx[tid + 3 * NN ] = x1;   // s11
    }
    #pragma unroll
    for (int j = tid; j < 4 * NN; j += 160) cv[j] = 0.f;
    __syncthreads();

    const float4* plane4 = (const float4*)(feat + (size_t)blk * (HH * WW));

    for (int t = 0; t < NTILE; t++) {
        // ---- load tile: 32 rows = 5120 floats = 1280 float4, 8 per thread ----
        const float4* tp = plane4 + t * (TROWS * WW / 4);
        #pragma unroll
        for (int it = 0; it < 8; it++) {
            const int j  = it * 160 + tid;     // float4 index in tile
            const int ry = j / 40;             // tile row
            const int x4 = j - ry * 40;        // float4 col
            const float4 v = tp[j];
            float* d = &s[ry * PSTR + x4 * 4];
            d[0] = v.x; d[1] = v.y; d[2] = v.z; d[3] = v.w;
        }
        __syncthreads();

        // ---- row scan pass 1: chunk sums (warp k handles 32-col chunk k of all rows) ----
        {
            float sum = 0.f;
            const float* p = &s[r * PSTR + k * 32];
            #pragma unroll
            for (int i = 0; i < 32; i++) sum += p[i];
            cs[k * 32 + r] = sum;
        }
        __syncthreads();

        // ---- row scan pass 2: inclusive scan with chunk offset ----
        {
            float run = 0.f;
            #pragma unroll
            for (int j = 0; j < 4; j++)
                if (j < k) run += cs[j * 32 + r];
            float* p = &s[r * PSTR + k * 32];
            #pragma unroll
            for (int i = 0; i < 32; i++) {
                run += p[i];
                p[i] = run;
            }
        }
        __syncthreads();

        // ---- column scan + carry: thread tid owns column tid ----
        {
            float run = carry[tid];
            #pragma unroll
            for (int ry = 0; ry < TROWS; ry++) {
                const int idx = ry * PSTR + tid;
                run += s[idx];
                s[idx] = run;           // s now holds SAT rows [32t .. 32t+31]
            }
            carry[tid] = run;
        }
        __syncthreads();

        // ---- corner harvest: SAT(y,x) for corners with y-1 in this tile ----
        #pragma unroll
        for (int j = tid; j < 4 * NN; j += 160) {
            const int y = cy[j];
            if (((y - 1) >> 5) == t && cx[j] >= 1)
                cv[j] = s[(y - 1 - t * TROWS) * PSTR + (cx[j] - 1)];
        }
        __syncthreads();
    }

    // ---- finalize boxes: thread n < 100 ----
    if (tid < NN) {
        const int x2 = cx[tid], y2 = cy[tid];
        const int x1 = cx[tid + 2 * NN], y1 = cy[tid + NN];
        float out = 0.f;
        if (x2 > x1 && y2 > y1) {
            const float sum = cv[tid] - cv[tid + NN] - cv[tid + 2 * NN] + cv[tid + 3 * NN];
            int area = (x2 - x1) * (y2 - y1);
            if (area < 1) area = 1;
            out = sum / (float)area;
        }
        g_pooled[((size_t)b * NN + tid) * CC + c] = out;
    }
}

// ---------------------------------------------------------------------------
// Kernel 2: segment mean per (b, cls) with negative-pixel fallback
// grid = B*NCLS blocks, 256 threads (one per channel)
// ---------------------------------------------------------------------------
__global__ void __launch_bounds__(256)
reduce_kernel(const float* __restrict__ feat,
              const float* __restrict__ boxes,
              const int*   __restrict__ gtc,
              const int*   __restrict__ neg_y,
              const int*   __restrict__ neg_x,
              const int*   __restrict__ img_h,
              const int*   __restrict__ img_w,
              float*       __restrict__ out)
{
    const int blk = blockIdx.x;               // b*NCLS + cls
    const int b   = blk / NCLS;
    const int cls = blk - b * NCLS;
    const int c   = threadIdx.x;              // 0..255

    __shared__ int   s_cls[NN];
    __shared__ float s_val[NN];

    if (c < NN) {
        s_cls[c] = gtc[b * NN + c];
        const float sx = (float)WW / (float)img_w[0];
        const float sy = (float)HH / (float)img_h[0];
        const float* bx = boxes + ((size_t)b * NN + c) * 4;
        const int x1 = (int)fminf(fmaxf(floorf(bx[0] * sx), 0.f), (float)WW);
        const int y1 = (int)fminf(fmaxf(floorf(bx[1] * sy), 0.f), (float)HH);
        const int x2 = (int)fminf(fmaxf(floorf(bx[2] * sx), 0.f), (float)WW);
        const int y2 = (int)fminf(fmaxf(floorf(bx[3] * sy), 0.f), (float)HH);
        s_val[c] = ((x2 > x1) && (y2 > y1)) ? 1.f : 0.f;
    }
    __syncthreads();

    float sum = 0.f;
    float cnt = 0.f;
    const float* pooled_b = g_pooled + (size_t)b * NN * CC;
    #pragma unroll 4
    for (int n = 0; n < NN; n++) {
        if (s_cls[n] == cls && s_val[n] > 0.f) {   // uniform across block
            sum += pooled_b[(size_t)n * CC + c];
            cnt += 1.f;
        }
    }

    float r;
    if (cnt > 0.f) {
        r = sum / cnt;
    } else {
        const int ny = neg_y[b * NCLS + cls];
        const int nx = neg_x[b * NCLS + cls];
        r = feat[(((size_t)b * CC + c) * HH + ny) * WW + nx];
    }
    out[(size_t)blk * CC + c] = r;
}

// ---------------------------------------------------------------------------
extern "C" void kernel_launch(void* const* d_in, const int* in_sizes, int n_in,
                              void* d_out, int out_size)
{
    const float* feat  = (const float*)d_in[0];   // [8,256,160,160] f32
    const float* boxes = (const float*)d_in[1];   // [8,100,4] f32
    const int*   gtc   = (const int*)d_in[2];     // [8,100] i32
    const int*   ngy   = (const int*)d_in[3];     // [8,80] i32
    const int*   ngx   = (const int*)d_in[4];     // [8,80] i32
    const int*   ih    = (const int*)d_in[5];     // scalar
    const int*   iw    = (const int*)d_in[6];     // scalar
    float*       out   = (float*)d_out;           // [8,80,256] f32

    sat_pool_kernel<<<BB * CC, 160>>>(feat, boxes, ih, iw);
    reduce_kernel<<<BB * NCLS, 256>>>(feat, boxes, gtc, ngy, ngx, ih, iw, out);
}